// round 1
// baseline (speedup 1.0000x reference)
#include <cuda_runtime.h>

// PMFlow: 6 steps of point-mass flow over 16 centers, B = 4194304 particles.
// Strategy: FMA-pipe bound compute kernel. Two particles packed per thread into
// f32x2 (Blackwell packed fp32) so every inner-loop ALU op processes both
// particles in one instruction. Center constants pre-negated + splatted into
// shared memory (LDS.64 broadcast rides MIO pipe, free under FMA-bound budget).
// rsqrt.approx / rcp.approx for the 1/r and 1/n terms (tolerance is 1e-3).

typedef unsigned long long u64;

#define NSTEPS  6
#define NCENT   16

// ---------- f32x2 packed helpers ----------
__device__ __forceinline__ u64 pk(float lo, float hi) {
    u64 r; asm("mov.b64 %0, {%1, %2};" : "=l"(r) : "f"(lo), "f"(hi)); return r;
}
__device__ __forceinline__ void upk(float& lo, float& hi, u64 v) {
    asm("mov.b64 {%0, %1}, %2;" : "=f"(lo), "=f"(hi) : "l"(v));
}
__device__ __forceinline__ u64 add2(u64 a, u64 b) {
    u64 d; asm("add.rn.f32x2 %0, %1, %2;" : "=l"(d) : "l"(a), "l"(b)); return d;
}
__device__ __forceinline__ u64 mul2(u64 a, u64 b) {
    u64 d; asm("mul.rn.f32x2 %0, %1, %2;" : "=l"(d) : "l"(a), "l"(b)); return d;
}
__device__ __forceinline__ u64 fma2(u64 a, u64 b, u64 c) {
    u64 d; asm("fma.rn.f32x2 %0, %1, %2, %3;" : "=l"(d) : "l"(a), "l"(b), "l"(c)); return d;
}
// packed rsqrt: two MUFU.RSQ, pair-packed via virtual regs (ptxas coalesces movs)
__device__ __forceinline__ u64 rsqrt2(u64 a) {
    u64 d;
    asm("{\n\t"
        ".reg .f32 lo, hi;\n\t"
        "mov.b64 {lo, hi}, %1;\n\t"
        "rsqrt.approx.f32 lo, lo;\n\t"
        "rsqrt.approx.f32 hi, hi;\n\t"
        "mov.b64 %0, {lo, hi};\n\t"
        "}" : "=l"(d) : "l"(a));
    return d;
}
__device__ __forceinline__ u64 rcp2(u64 a) {
    u64 d;
    asm("{\n\t"
        ".reg .f32 lo, hi;\n\t"
        "mov.b64 {lo, hi}, %1;\n\t"
        "rcp.approx.f32 lo, lo;\n\t"
        "rcp.approx.f32 hi, hi;\n\t"
        "mov.b64 %0, {lo, hi};\n\t"
        "}" : "=l"(d) : "l"(a));
    return d;
}

__global__ __launch_bounds__(256)
void pmflow_kernel(const float4* __restrict__ z,
                   const float*  __restrict__ centers,
                   const float*  __restrict__ mus,
                   float4* __restrict__ out,
                   int nvec)
{
    // pre-splatted packed constants: (-cx,-cx), (-cy,-cy), (mu,mu)
    __shared__ u64 s_ncx[NCENT];
    __shared__ u64 s_ncy[NCENT];
    __shared__ u64 s_mu [NCENT];
    if (threadIdx.x < NCENT) {
        int k = threadIdx.x;
        float cx = centers[2 * k + 0];
        float cy = centers[2 * k + 1];
        float m  = mus[k];
        s_ncx[k] = pk(-cx, -cx);
        s_ncy[k] = pk(-cy, -cy);
        s_mu [k] = pk(m, m);
    }
    __syncthreads();

    int i = blockIdx.x * blockDim.x + threadIdx.x;
    if (i >= nvec) return;

    // one float4 = two particles (x0,y0,x1,y1); pack cross-particle
    float4 zz = z[i];
    u64 X = pk(zz.x, zz.z);
    u64 Y = pk(zz.y, zz.w);

    const u64 EPS2 = pk(1e-4f, 1e-4f);
    const u64 ONE2 = pk(1.0f, 1.0f);
    const u64 NDT2 = pk(-0.2f, -0.2f);   // -DT  (g = -G/n, so step = -DT/n * G)
    const u64 ADV2 = pk(0.01f, 0.01f);   // DT * ADVECT on y

    #pragma unroll 1
    for (int s = 0; s < NSTEPS; ++s) {
        u64 N  = ONE2;      // n = 1 + sum(mu/r)
        u64 GX = 0ull;      // (0.0f, 0.0f)
        u64 GY = 0ull;

        #pragma unroll
        for (int k = 0; k < NCENT; ++k) {
            u64 ncx = s_ncx[k];
            u64 ncy = s_ncy[k];
            u64 mu  = s_mu [k];
            u64 dX = add2(X, ncx);                 // z - c
            u64 dY = add2(Y, ncy);
            u64 R2 = fma2(dX, dX, EPS2);           // dx^2 + dy^2 + eps
            R2     = fma2(dY, dY, R2);
            u64 RI = rsqrt2(R2);                   // 1/r
            u64 MR = mul2(mu, RI);                 // mu/r
            N      = add2(N, MR);
            u64 W  = mul2(MR, mul2(RI, RI));       // mu/r^3
            GX     = fma2(W, dX, GX);              // G += w * rvec
            GY     = fma2(W, dY, GY);
        }

        u64 S = mul2(rcp2(N), NDT2);               // -DT / n
        X = fma2(S, GX, X);                        // z += DT * g
        Y = fma2(S, GY, add2(Y, ADV2));            // + DT*advect on y

        // clip to [-3, 3] (scalar FMNMX; no packed min/max)
        float x0, x1, y0, y1;
        upk(x0, x1, X);
        upk(y0, y1, Y);
        x0 = fminf(fmaxf(x0, -3.0f), 3.0f);
        x1 = fminf(fmaxf(x1, -3.0f), 3.0f);
        y0 = fminf(fmaxf(y0, -3.0f), 3.0f);
        y1 = fminf(fmaxf(y1, -3.0f), 3.0f);
        X = pk(x0, x1);
        Y = pk(y0, y1);
    }

    float x0, x1, y0, y1;
    upk(x0, x1, X);
    upk(y0, y1, Y);
    out[i] = make_float4(x0, y0, x1, y1);
}

extern "C" void kernel_launch(void* const* d_in, const int* in_sizes, int n_in,
                              void* d_out, int out_size)
{
    const float4* z       = (const float4*)d_in[0];
    const float*  centers = (const float*)d_in[1];
    const float*  mus     = (const float*)d_in[2];
    float4*       out     = (float4*)d_out;

    int nvec = in_sizes[0] / 4;              // float4 count = 2 particles each
    int threads = 256;
    int blocks = (nvec + threads - 1) / threads;
    pmflow_kernel<<<blocks, threads>>>(z, centers, mus, out, nvec);
}

// round 4
// speedup vs baseline: 1.0482x; 1.0482x over previous
#include <cuda_runtime.h>

// PMFlow: 6 steps of point-mass flow over 16 centers, B = 4194304 particles.
// R2/R3 were infra failures (broker could not hold a container; kernel never ran).
// R4 = third submission of the same single-variable experiment:
// __launch_bounds__(256, 4) caps regs at 64 (was 128) to lift occupancy from
// 23.8% -> ~50%. R1 evidence showed issue=55.8%, occ=23.8%, fma=66%:
// issue/latency-bound, not pipe-bound; the f32x2 instruction mix is already
// near the FMA-pipe floor (~112us). Everything else (f32x2 packing,
// smem-broadcast constants, approx rsqrt/rcp) kept from the passing R1 kernel
// (203us, rel_err 3.9e-4).

typedef unsigned long long u64;

#define NSTEPS  6
#define NCENT   16

// ---------- f32x2 packed helpers ----------
__device__ __forceinline__ u64 pk(float lo, float hi) {
    u64 r; asm("mov.b64 %0, {%1, %2};" : "=l"(r) : "f"(lo), "f"(hi)); return r;
}
__device__ __forceinline__ void upk(float& lo, float& hi, u64 v) {
    asm("mov.b64 {%0, %1}, %2;" : "=f"(lo), "=f"(hi) : "l"(v));
}
__device__ __forceinline__ u64 add2(u64 a, u64 b) {
    u64 d; asm("add.rn.f32x2 %0, %1, %2;" : "=l"(d) : "l"(a), "l"(b)); return d;
}
__device__ __forceinline__ u64 mul2(u64 a, u64 b) {
    u64 d; asm("mul.rn.f32x2 %0, %1, %2;" : "=l"(d) : "l"(a), "l"(b)); return d;
}
__device__ __forceinline__ u64 fma2(u64 a, u64 b, u64 c) {
    u64 d; asm("fma.rn.f32x2 %0, %1, %2, %3;" : "=l"(d) : "l"(a), "l"(b), "l"(c)); return d;
}
// packed rsqrt: two MUFU.RSQ; the b64 movs alias register pairs and mostly vanish
__device__ __forceinline__ u64 rsqrt2(u64 a) {
    u64 d;
    asm("{\n\t"
        ".reg .f32 lo, hi;\n\t"
        "mov.b64 {lo, hi}, %1;\n\t"
        "rsqrt.approx.f32 lo, lo;\n\t"
        "rsqrt.approx.f32 hi, hi;\n\t"
        "mov.b64 %0, {lo, hi};\n\t"
        "}" : "=l"(d) : "l"(a));
    return d;
}
__device__ __forceinline__ u64 rcp2(u64 a) {
    u64 d;
    asm("{\n\t"
        ".reg .f32 lo, hi;\n\t"
        "mov.b64 {lo, hi}, %1;\n\t"
        "rcp.approx.f32 lo, lo;\n\t"
        "rcp.approx.f32 hi, hi;\n\t"
        "mov.b64 %0, {lo, hi};\n\t"
        "}" : "=l"(d) : "l"(a));
    return d;
}

__global__ __launch_bounds__(256, 4)   // <= 64 regs: 4 CTAs/SM, 32 warps/SM
void pmflow_kernel(const float4* __restrict__ z,
                   const float*  __restrict__ centers,
                   const float*  __restrict__ mus,
                   float4* __restrict__ out,
                   int nvec)
{
    // pre-splatted packed constants: (-cx,-cx), (-cy,-cy), (mu,mu)
    __shared__ u64 s_ncx[NCENT];
    __shared__ u64 s_ncy[NCENT];
    __shared__ u64 s_mu [NCENT];
    if (threadIdx.x < NCENT) {
        int k = threadIdx.x;
        float cx = centers[2 * k + 0];
        float cy = centers[2 * k + 1];
        float m  = mus[k];
        s_ncx[k] = pk(-cx, -cx);
        s_ncy[k] = pk(-cy, -cy);
        s_mu [k] = pk(m, m);
    }
    __syncthreads();

    int i = blockIdx.x * blockDim.x + threadIdx.x;
    if (i >= nvec) return;

    // one float4 = two particles (x0,y0,x1,y1); pack cross-particle
    float4 zz = z[i];
    u64 X = pk(zz.x, zz.z);
    u64 Y = pk(zz.y, zz.w);

    const u64 EPS2 = pk(1e-4f, 1e-4f);
    const u64 ONE2 = pk(1.0f, 1.0f);
    const u64 NDT2 = pk(-0.2f, -0.2f);   // -DT  (g = -G/n, so step = -DT/n * G)
    const u64 ADV2 = pk(0.01f, 0.01f);   // DT * ADVECT on y

    #pragma unroll 1
    for (int s = 0; s < NSTEPS; ++s) {
        u64 N  = ONE2;      // n = 1 + sum(mu/r)
        u64 GX = 0ull;
        u64 GY = 0ull;

        #pragma unroll
        for (int k = 0; k < NCENT; ++k) {
            u64 ncx = s_ncx[k];
            u64 ncy = s_ncy[k];
            u64 mu  = s_mu [k];
            u64 dX = add2(X, ncx);                 // z - c
            u64 dY = add2(Y, ncy);
            u64 R2 = fma2(dX, dX, EPS2);           // dx^2 + dy^2 + eps
            R2     = fma2(dY, dY, R2);
            u64 RI = rsqrt2(R2);                   // 1/r
            u64 MR = mul2(mu, RI);                 // mu/r
            N      = add2(N, MR);
            u64 W  = mul2(MR, mul2(RI, RI));       // mu/r^3
            GX     = fma2(W, dX, GX);              // G += w * rvec
            GY     = fma2(W, dY, GY);
        }

        u64 S = mul2(rcp2(N), NDT2);               // -DT / n
        X = fma2(S, GX, X);                        // z += DT * g
        Y = fma2(S, GY, add2(Y, ADV2));            // + DT*advect on y

        // clip to [-3, 3]
        float x0, x1, y0, y1;
        upk(x0, x1, X);
        upk(y0, y1, Y);
        x0 = fminf(fmaxf(x0, -3.0f), 3.0f);
        x1 = fminf(fmaxf(x1, -3.0f), 3.0f);
        y0 = fminf(fmaxf(y0, -3.0f), 3.0f);
        y1 = fminf(fmaxf(y1, -3.0f), 3.0f);
        X = pk(x0, x1);
        Y = pk(y0, y1);
    }

    float x0, x1, y0, y1;
    upk(x0, x1, X);
    upk(y0, y1, Y);
    out[i] = make_float4(x0, y0, x1, y1);
}

extern "C" void kernel_launch(void* const* d_in, const int* in_sizes, int n_in,
                              void* d_out, int out_size)
{
    const float4* z       = (const float4*)d_in[0];
    const float*  centers = (const float*)d_in[1];
    const float*  mus     = (const float*)d_in[2];
    float4*       out     = (float4*)d_out;

    int nvec = in_sizes[0] / 4;              // float4 count = 2 particles each
    int threads = 256;
    int blocks = (nvec + threads - 1) / threads;
    pmflow_kernel<<<blocks, threads>>>(z, centers, mus, out, nvec);
}